// round 7
// baseline (speedup 1.0000x reference)
#include <cuda_runtime.h>
#include <cstdint>

#define BB 4
#define CC 256
#define HH 56
#define WW 56
#define CR 64          // C / 4
#define GG 16          // groups
#define GC 16
#define KK 7
#define K2T 49
#define M2 784         // GG * K2T
#define HW 3136        // HH * WW
#define PAD 3

typedef unsigned long long u64;

// Scratch (__device__ globals; no allocations allowed)
__device__ float g_w1[BB * CR * HW];        // [B, Cr, HW]
__device__ float g_w2[BB * M2 * HW];        // [B, G*49, HW]

// ---- packed f32x2 helpers (base sm_100-family PTX, no 'a' feature) --------
__device__ __forceinline__ u64 pack2(float x, float y) {
    u64 d;
    asm("mov.b64 %0, {%1, %2};" : "=l"(d) : "f"(x), "f"(y));
    return d;
}
__device__ __forceinline__ void unpack2(float& x, float& y, u64 v) {
    asm("mov.b64 {%0, %1}, %2;" : "=f"(x), "=f"(y) : "l"(v));
}
__device__ __forceinline__ void ffma2(u64& acc, u64 a, u64 b) {
    asm("fma.rn.f32x2 %0, %1, %2, %0;" : "+l"(acc) : "l"(a), "l"(b));
}

// ---------------------------------------------------------------------------
// K1: w1 = relu(bn(conv1_1x1(x))).  GEMM [64 x 256] x [256 x 3136] per batch.
// Tile 64o x 32px, 128 threads, 4x4 per thread, k-step 64. (round-5, 21us)
// ---------------------------------------------------------------------------
__global__ __launch_bounds__(128) void k1_conv1_bn_relu(
        const float* __restrict__ x,
        const float* __restrict__ w1w,
        const float* __restrict__ gamma,
        const float* __restrict__ beta,
        const float* __restrict__ mean,
        const float* __restrict__ var) {
    __shared__ float As[64 * 68];    // [k][o]
    __shared__ float Bs[64 * 32];    // [k][px]

    const int tid = threadIdx.x;
    const int tx = tid & 7;
    const int ty = tid >> 3;
    const int px0 = blockIdx.x * 32;
    const int b = blockIdx.y;

    float acc[4][4];
#pragma unroll
    for (int i = 0; i < 4; ++i)
#pragma unroll
        for (int u = 0; u < 4; ++u) acc[i][u] = 0.f;

    for (int kt = 0; kt < CC; kt += 64) {
        {
            int k = tid & 63;
            int oh = tid >> 6;
#pragma unroll
            for (int r = 0; r < 32; ++r) {
                int o = 2 * r + oh;
                As[k * 68 + o] = w1w[o * CC + kt + k];
            }
        }
        {
            int j = tid & 31;
            int kh = tid >> 5;
#pragma unroll
            for (int r = 0; r < 16; ++r) {
                int k = 4 * r + kh;
                Bs[k * 32 + j] = x[(size_t)(b * CC + kt + k) * HW + px0 + j];
            }
        }
        __syncthreads();

#pragma unroll 16
        for (int k = 0; k < 64; ++k) {
            float4 av = *(const float4*)&As[k * 68 + ty * 4];
            float4 bv = *(const float4*)&Bs[k * 32 + tx * 4];
            acc[0][0] = fmaf(av.x, bv.x, acc[0][0]);
            acc[0][1] = fmaf(av.x, bv.y, acc[0][1]);
            acc[0][2] = fmaf(av.x, bv.z, acc[0][2]);
            acc[0][3] = fmaf(av.x, bv.w, acc[0][3]);
            acc[1][0] = fmaf(av.y, bv.x, acc[1][0]);
            acc[1][1] = fmaf(av.y, bv.y, acc[1][1]);
            acc[1][2] = fmaf(av.y, bv.z, acc[1][2]);
            acc[1][3] = fmaf(av.y, bv.w, acc[1][3]);
            acc[2][0] = fmaf(av.z, bv.x, acc[2][0]);
            acc[2][1] = fmaf(av.z, bv.y, acc[2][1]);
            acc[2][2] = fmaf(av.z, bv.z, acc[2][2]);
            acc[2][3] = fmaf(av.z, bv.w, acc[2][3]);
            acc[3][0] = fmaf(av.w, bv.x, acc[3][0]);
            acc[3][1] = fmaf(av.w, bv.y, acc[3][1]);
            acc[3][2] = fmaf(av.w, bv.z, acc[3][2]);
            acc[3][3] = fmaf(av.w, bv.w, acc[3][3]);
        }
        __syncthreads();
    }

#pragma unroll
    for (int i = 0; i < 4; ++i) {
        int o = ty * 4 + i;
        float sc = gamma[o] * rsqrtf(var[o] + 1e-5f);
        float sh = beta[o] - mean[o] * sc;
        float4 v;
        v.x = fmaxf(fmaf(acc[i][0], sc, sh), 0.f);
        v.y = fmaxf(fmaf(acc[i][1], sc, sh), 0.f);
        v.z = fmaxf(fmaf(acc[i][2], sc, sh), 0.f);
        v.w = fmaxf(fmaf(acc[i][3], sc, sh), 0.f);
        *(float4*)(g_w1 + (size_t)(b * CR + o) * HW + px0 + tx * 4) = v;
    }
}

// ---------------------------------------------------------------------------
// K2: w2 = conv2_1x1(w1) + bias.  GEMM [784 x 64] x [64 x 3136] per batch.
// Tile 64o x 64px, 64 threads, 8x8 per thread, K=64. Mainloop in packed
// fma.rn.f32x2: 32 FFMA2 + 12 packs per k instead of 64 FFMA.
// ---------------------------------------------------------------------------
__global__ __launch_bounds__(64) void k2_conv2(
        const float* __restrict__ w2w,
        const float* __restrict__ w2b) {
    __shared__ float As[64 * 68];    // [k][o]
    __shared__ float Bs[64 * 64];    // [k][px]

    const int tid = threadIdx.x;
    const int tx = tid & 7;          // px octet
    const int ty = tid >> 3;         // o octet
    const int px0 = blockIdx.x * 64; // 49*64 = 3136 exact
    const int o0 = blockIdx.y * 64;  // 13 tiles (832), guard at 784
    const int b = blockIdx.z;

#pragma unroll
    for (int r = 0; r < 64; ++r)
        As[tid * 68 + r] = (o0 + r < M2) ? w2w[(o0 + r) * CR + tid] : 0.f;
#pragma unroll
    for (int r = 0; r < 64; ++r)
        Bs[r * 64 + tid] = g_w1[(size_t)(b * CR + r) * HW + px0 + tid];
    __syncthreads();

    u64 acc2[8][4];
#pragma unroll
    for (int i = 0; i < 8; ++i)
#pragma unroll
        for (int u = 0; u < 4; ++u) acc2[i][u] = 0ull;

#pragma unroll 4
    for (int k = 0; k < 64; ++k) {
        float4 a0 = *(const float4*)&As[k * 68 + ty * 8];
        float4 a1 = *(const float4*)&As[k * 68 + ty * 8 + 4];
        float4 b0 = *(const float4*)&Bs[k * 64 + tx * 8];
        float4 b1 = *(const float4*)&Bs[k * 64 + tx * 8 + 4];
        u64 aa[8];
        aa[0] = pack2(a0.x, a0.x); aa[1] = pack2(a0.y, a0.y);
        aa[2] = pack2(a0.z, a0.z); aa[3] = pack2(a0.w, a0.w);
        aa[4] = pack2(a1.x, a1.x); aa[5] = pack2(a1.y, a1.y);
        aa[6] = pack2(a1.z, a1.z); aa[7] = pack2(a1.w, a1.w);
        u64 bb[4];
        bb[0] = pack2(b0.x, b0.y); bb[1] = pack2(b0.z, b0.w);
        bb[2] = pack2(b1.x, b1.y); bb[3] = pack2(b1.z, b1.w);
#pragma unroll
        for (int i = 0; i < 8; ++i)
#pragma unroll
            for (int u = 0; u < 4; ++u)
                ffma2(acc2[i][u], aa[i], bb[u]);
    }

#pragma unroll
    for (int i = 0; i < 8; ++i) {
        int o = o0 + ty * 8 + i;
        if (o >= M2) continue;
        float bias = w2b[o];
        float p[8];
        unpack2(p[0], p[1], acc2[i][0]);
        unpack2(p[2], p[3], acc2[i][1]);
        unpack2(p[4], p[5], acc2[i][2]);
        unpack2(p[6], p[7], acc2[i][3]);
        float* dst = g_w2 + (size_t)(b * M2 + o) * HW + px0 + tx * 8;
        float4 v0, v1;
        v0.x = p[0] + bias; v0.y = p[1] + bias;
        v0.z = p[2] + bias; v0.w = p[3] + bias;
        v1.x = p[4] + bias; v1.y = p[5] + bias;
        v1.z = p[6] + bias; v1.w = p[7] + bias;
        *(float4*)dst = v0;
        *(float4*)(dst + 4) = v1;
    }
}

// ---------------------------------------------------------------------------
// K3: involution reduce. Block = (4-row band, group, batch); 224 threads.
// Thread = 4 px x 4 ch. (round-4 best, unchanged)
// ---------------------------------------------------------------------------
__global__ __launch_bounds__(224) void k3_involution(
        const float* __restrict__ x,
        float* __restrict__ out) {
    __shared__ float xs[GC * 10 * 64];

    const int tid = threadIdx.x;
    const int h0 = blockIdx.x * 4;
    const int g = blockIdx.y;
    const int b = blockIdx.z;

    const float* xg = x + (size_t)(b * CC + g * GC) * HW;
    for (int i = tid; i < GC * 10 * 64; i += 224) {
        int ch = i / 640;
        int rem = i - ch * 640;
        int rr = rem >> 6;
        int c = rem & 63;
        int hh = h0 - 3 + rr;
        int ww = c - 3;
        float v = 0.f;
        if (hh >= 0 && hh < HH && ww >= 0 && ww < WW)
            v = xg[(size_t)ch * HW + hh * WW + ww];
        xs[i] = v;
    }
    __syncthreads();

    const int q = tid % 14;
    const int cg = (tid / 14) & 3;
    const int r = tid / 56;
    const int w0 = q * 4;
    const int h = h0 + r;

    const float* wg = g_w2 + ((size_t)(b * GG + g) * K2T) * HW + h * WW + w0;

    float acc[4][4];
#pragma unroll
    for (int c = 0; c < 4; ++c)
#pragma unroll
        for (int p = 0; p < 4; ++p) acc[c][p] = 0.f;

#pragma unroll
    for (int ki = 0; ki < KK; ++ki) {
        float4 wv[7];
#pragma unroll
        for (int kj = 0; kj < KK; ++kj)
            wv[kj] = *(const float4*)(wg + (size_t)(ki * KK + kj) * HW);
#pragma unroll
        for (int c = 0; c < 4; ++c) {
            const float* xr = &xs[(cg * 4 + c) * 640 + (r + ki) * 64 + w0];
            float4 xa = *(const float4*)(xr);
            float4 xb = *(const float4*)(xr + 4);
            float4 xc = *(const float4*)(xr + 8);
            float xw[12] = {xa.x, xa.y, xa.z, xa.w,
                            xb.x, xb.y, xb.z, xb.w,
                            xc.x, xc.y, xc.z, xc.w};
#pragma unroll
            for (int kj = 0; kj < KK; ++kj) {
                acc[c][0] = fmaf(wv[kj].x, xw[kj + 0], acc[c][0]);
                acc[c][1] = fmaf(wv[kj].y, xw[kj + 1], acc[c][1]);
                acc[c][2] = fmaf(wv[kj].z, xw[kj + 2], acc[c][2]);
                acc[c][3] = fmaf(wv[kj].w, xw[kj + 3], acc[c][3]);
            }
        }
    }

#pragma unroll
    for (int c = 0; c < 4; ++c) {
        float4 v = make_float4(acc[c][0], acc[c][1], acc[c][2], acc[c][3]);
        *(float4*)(out + (size_t)(b * CC + g * GC + cg * 4 + c) * HW
                   + h * WW + w0) = v;
    }
}

// ---------------------------------------------------------------------------
extern "C" void kernel_launch(void* const* d_in, const int* in_sizes, int n_in,
                              void* d_out, int out_size) {
    const float* x     = (const float*)d_in[0];
    const float* w1w   = (const float*)d_in[1];
    const float* gamma = (const float*)d_in[2];
    const float* beta  = (const float*)d_in[3];
    const float* mean  = (const float*)d_in[4];
    const float* var   = (const float*)d_in[5];
    const float* w2w   = (const float*)d_in[6];
    const float* w2b   = (const float*)d_in[7];
    float* out = (float*)d_out;

    dim3 g1(HW / 32, BB);                       // 98 x 4 = 392
    k1_conv1_bn_relu<<<g1, 128>>>(x, w1w, gamma, beta, mean, var);

    dim3 g2(HW / 64, (M2 + 63) / 64, BB);       // 49 x 13 x 4 = 2548
    k2_conv2<<<g2, 64>>>(w2w, w2b);

    dim3 g3(HH / 4, GG, BB);                    // 14 x 16 x 4 = 896
    k3_involution<<<g3, 224>>>(x, out);
}

// round 8
// speedup vs baseline: 1.0246x; 1.0246x over previous
#include <cuda_runtime.h>
#include <cstdint>

#define BB 4
#define CC 256
#define HH 56
#define WW 56
#define CR 64          // C / 4
#define GG 16          // groups
#define GC 16
#define KK 7
#define K2T 49
#define M2 784         // GG * K2T
#define HW 3136        // HH * WW
#define PAD 3
#define N1 (BB * CR * HW)   // 802816

// Scratch (__device__ globals; no allocations allowed)
__device__ float g_p[2 * N1];               // K1 split-K partials
__device__ float g_w1[N1];                  // [B, Cr, HW]
__device__ float g_w2[BB * M2 * HW];        // [B, G*49, HW]

// ---------------------------------------------------------------------------
// K1a: partial conv1 over half the C range (split-K = 2).
// Tile 64o x 32px x 128k, 128 threads, 4x4 per thread, 2 k-steps of 64.
// Grid: 98 x 4 x 2 = 784 blocks (3136 warps resident, occ ~33%).
// ---------------------------------------------------------------------------
__global__ __launch_bounds__(128) void k1a_partial(
        const float* __restrict__ x,
        const float* __restrict__ w1w) {
    __shared__ float As[64 * 68];    // [k][o]
    __shared__ float Bs[64 * 32];    // [k][px]

    const int tid = threadIdx.x;
    const int tx = tid & 7;          // px quad (8 quads = 32 px)
    const int ty = tid >> 3;         // o quad (16 quads = 64 o)
    const int px0 = blockIdx.x * 32; // 98*32 = 3136 exact
    const int b = blockIdx.y;
    const int ks = blockIdx.z;       // k slice (0/1)

    float acc[4][4];
#pragma unroll
    for (int i = 0; i < 4; ++i)
#pragma unroll
        for (int u = 0; u < 4; ++u) acc[i][u] = 0.f;

    for (int kt = ks * 128; kt < ks * 128 + 128; kt += 64) {
        {
            int k = tid & 63;
            int oh = tid >> 6;
#pragma unroll
            for (int r = 0; r < 32; ++r) {
                int o = 2 * r + oh;
                As[k * 68 + o] = w1w[o * CC + kt + k];
            }
        }
        {
            int j = tid & 31;
            int kh = tid >> 5;
#pragma unroll
            for (int r = 0; r < 16; ++r) {
                int k = 4 * r + kh;
                Bs[k * 32 + j] = x[(size_t)(b * CC + kt + k) * HW + px0 + j];
            }
        }
        __syncthreads();

#pragma unroll 16
        for (int k = 0; k < 64; ++k) {
            float4 av = *(const float4*)&As[k * 68 + ty * 4];
            float4 bv = *(const float4*)&Bs[k * 32 + tx * 4];
            acc[0][0] = fmaf(av.x, bv.x, acc[0][0]);
            acc[0][1] = fmaf(av.x, bv.y, acc[0][1]);
            acc[0][2] = fmaf(av.x, bv.z, acc[0][2]);
            acc[0][3] = fmaf(av.x, bv.w, acc[0][3]);
            acc[1][0] = fmaf(av.y, bv.x, acc[1][0]);
            acc[1][1] = fmaf(av.y, bv.y, acc[1][1]);
            acc[1][2] = fmaf(av.y, bv.z, acc[1][2]);
            acc[1][3] = fmaf(av.y, bv.w, acc[1][3]);
            acc[2][0] = fmaf(av.z, bv.x, acc[2][0]);
            acc[2][1] = fmaf(av.z, bv.y, acc[2][1]);
            acc[2][2] = fmaf(av.z, bv.z, acc[2][2]);
            acc[2][3] = fmaf(av.z, bv.w, acc[2][3]);
            acc[3][0] = fmaf(av.w, bv.x, acc[3][0]);
            acc[3][1] = fmaf(av.w, bv.y, acc[3][1]);
            acc[3][2] = fmaf(av.w, bv.z, acc[3][2]);
            acc[3][3] = fmaf(av.w, bv.w, acc[3][3]);
        }
        __syncthreads();
    }

#pragma unroll
    for (int i = 0; i < 4; ++i) {
        int o = ty * 4 + i;
        float4 v = make_float4(acc[i][0], acc[i][1], acc[i][2], acc[i][3]);
        *(float4*)(g_p + (size_t)ks * N1 + (size_t)(b * CR + o) * HW
                   + px0 + tx * 4) = v;
    }
}

// ---------------------------------------------------------------------------
// K1b: sum partials + BN(eval) + ReLU.  Elementwise, float4-vectorized.
// ---------------------------------------------------------------------------
__global__ __launch_bounds__(256) void k1b_bn_relu(
        const float* __restrict__ gamma,
        const float* __restrict__ beta,
        const float* __restrict__ mean,
        const float* __restrict__ var) {
    int i4 = blockIdx.x * blockDim.x + threadIdx.x;   // float4 index
    if (i4 >= N1 / 4) return;
    int idx = i4 * 4;
    int o = (idx / HW) % CR;                          // same o across the 4

    float sc = gamma[o] * rsqrtf(var[o] + 1e-5f);
    float sh = beta[o] - mean[o] * sc;

    float4 p0 = *(const float4*)(g_p + idx);
    float4 p1 = *(const float4*)(g_p + N1 + idx);
    float4 v;
    v.x = fmaxf(fmaf(p0.x + p1.x, sc, sh), 0.f);
    v.y = fmaxf(fmaf(p0.y + p1.y, sc, sh), 0.f);
    v.z = fmaxf(fmaf(p0.z + p1.z, sc, sh), 0.f);
    v.w = fmaxf(fmaf(p0.w + p1.w, sc, sh), 0.f);
    *(float4*)(g_w1 + idx) = v;
}

// ---------------------------------------------------------------------------
// K2: w2 = conv2_1x1(w1) + bias.  GEMM [784 x 64] x [64 x 3136] per batch.
// Tile 64o x 64px, 128 threads (4 warps), 8x4 per thread, K=64 one shot.
// ---------------------------------------------------------------------------
__global__ __launch_bounds__(128) void k2_conv2(
        const float* __restrict__ w2w,
        const float* __restrict__ w2b) {
    __shared__ float As[64 * 68];    // [k][o]
    __shared__ float Bs[64 * 64];    // [k][px]

    const int tid = threadIdx.x;
    const int tx = tid & 15;         // px quad (16 quads = 64 px)
    const int ty = tid >> 4;         // o octet (8 octets = 64 o)
    const int px0 = blockIdx.x * 64; // 49*64 = 3136 exact
    const int o0 = blockIdx.y * 64;  // 13 tiles (832), guard at 784
    const int b = blockIdx.z;

    // As: [k][o], coalesced along k
    {
        int k = tid & 63;
        int oh = tid >> 6;           // 0/1
#pragma unroll
        for (int r = 0; r < 32; ++r) {
            int o = 2 * r + oh;
            As[k * 68 + o] = (o0 + o < M2) ? w2w[(o0 + o) * CR + k] : 0.f;
        }
    }
    // Bs: [k][px], coalesced along px
    {
        int j = tid & 63;
        int kh = tid >> 6;           // 0/1
#pragma unroll
        for (int r = 0; r < 32; ++r) {
            int k = 2 * r + kh;
            Bs[k * 64 + j] = g_w1[(size_t)(b * CR + k) * HW + px0 + j];
        }
    }
    __syncthreads();

    float acc[8][4];
#pragma unroll
    for (int i = 0; i < 8; ++i)
#pragma unroll
        for (int u = 0; u < 4; ++u) acc[i][u] = 0.f;

#pragma unroll 8
    for (int k = 0; k < 64; ++k) {
        float4 a0 = *(const float4*)&As[k * 68 + ty * 8];
        float4 a1 = *(const float4*)&As[k * 68 + ty * 8 + 4];
        float4 bv = *(const float4*)&Bs[k * 64 + tx * 4];
        float av[8] = {a0.x, a0.y, a0.z, a0.w, a1.x, a1.y, a1.z, a1.w};
#pragma unroll
        for (int i = 0; i < 8; ++i) {
            acc[i][0] = fmaf(av[i], bv.x, acc[i][0]);
            acc[i][1] = fmaf(av[i], bv.y, acc[i][1]);
            acc[i][2] = fmaf(av[i], bv.z, acc[i][2]);
            acc[i][3] = fmaf(av[i], bv.w, acc[i][3]);
        }
    }

#pragma unroll
    for (int i = 0; i < 8; ++i) {
        int o = o0 + ty * 8 + i;
        if (o >= M2) continue;
        float bias = w2b[o];
        float4 v;
        v.x = acc[i][0] + bias;
        v.y = acc[i][1] + bias;
        v.z = acc[i][2] + bias;
        v.w = acc[i][3] + bias;
        *(float4*)(g_w2 + (size_t)(b * M2 + o) * HW + px0 + tx * 4) = v;
    }
}

// ---------------------------------------------------------------------------
// K3: involution reduce. Block = (4-row band, group, batch); 224 threads.
// Thread = 4 px x 4 ch. (round-4 best, unchanged)
// ---------------------------------------------------------------------------
__global__ __launch_bounds__(224) void k3_involution(
        const float* __restrict__ x,
        float* __restrict__ out) {
    __shared__ float xs[GC * 10 * 64];

    const int tid = threadIdx.x;
    const int h0 = blockIdx.x * 4;
    const int g = blockIdx.y;
    const int b = blockIdx.z;

    const float* xg = x + (size_t)(b * CC + g * GC) * HW;
    for (int i = tid; i < GC * 10 * 64; i += 224) {
        int ch = i / 640;
        int rem = i - ch * 640;
        int rr = rem >> 6;
        int c = rem & 63;
        int hh = h0 - 3 + rr;
        int ww = c - 3;
        float v = 0.f;
        if (hh >= 0 && hh < HH && ww >= 0 && ww < WW)
            v = xg[(size_t)ch * HW + hh * WW + ww];
        xs[i] = v;
    }
    __syncthreads();

    const int q = tid % 14;
    const int cg = (tid / 14) & 3;
    const int r = tid / 56;
    const int w0 = q * 4;
    const int h = h0 + r;

    const float* wg = g_w2 + ((size_t)(b * GG + g) * K2T) * HW + h * WW + w0;

    float acc[4][4];
#pragma unroll
    for (int c = 0; c < 4; ++c)
#pragma unroll
        for (int p = 0; p < 4; ++p) acc[c][p] = 0.f;

#pragma unroll
    for (int ki = 0; ki < KK; ++ki) {
        float4 wv[7];
#pragma unroll
        for (int kj = 0; kj < KK; ++kj)
            wv[kj] = *(const float4*)(wg + (size_t)(ki * KK + kj) * HW);
#pragma unroll
        for (int c = 0; c < 4; ++c) {
            const float* xr = &xs[(cg * 4 + c) * 640 + (r + ki) * 64 + w0];
            float4 xa = *(const float4*)(xr);
            float4 xb = *(const float4*)(xr + 4);
            float4 xc = *(const float4*)(xr + 8);
            float xw[12] = {xa.x, xa.y, xa.z, xa.w,
                            xb.x, xb.y, xb.z, xb.w,
                            xc.x, xc.y, xc.z, xc.w};
#pragma unroll
            for (int kj = 0; kj < KK; ++kj) {
                acc[c][0] = fmaf(wv[kj].x, xw[kj + 0], acc[c][0]);
                acc[c][1] = fmaf(wv[kj].y, xw[kj + 1], acc[c][1]);
                acc[c][2] = fmaf(wv[kj].z, xw[kj + 2], acc[c][2]);
                acc[c][3] = fmaf(wv[kj].w, xw[kj + 3], acc[c][3]);
            }
        }
    }

#pragma unroll
    for (int c = 0; c < 4; ++c) {
        float4 v = make_float4(acc[c][0], acc[c][1], acc[c][2], acc[c][3]);
        *(float4*)(out + (size_t)(b * CC + g * GC + cg * 4 + c) * HW
                   + h * WW + w0) = v;
    }
}

// ---------------------------------------------------------------------------
extern "C" void kernel_launch(void* const* d_in, const int* in_sizes, int n_in,
                              void* d_out, int out_size) {
    const float* x     = (const float*)d_in[0];
    const float* w1w   = (const float*)d_in[1];
    const float* gamma = (const float*)d_in[2];
    const float* beta  = (const float*)d_in[3];
    const float* mean  = (const float*)d_in[4];
    const float* var   = (const float*)d_in[5];
    const float* w2w   = (const float*)d_in[6];
    const float* w2b   = (const float*)d_in[7];
    float* out = (float*)d_out;

    dim3 g1(HW / 32, BB, 2);                    // 98 x 4 x 2 = 784
    k1a_partial<<<g1, 128>>>(x, w1w);

    k1b_bn_relu<<<(N1 / 4 + 255) / 256, 256>>>(gamma, beta, mean, var);

    dim3 g2(HW / 64, (M2 + 63) / 64, BB);       // 49 x 13 x 4 = 2548
    k2_conv2<<<g2, 128>>>(w2w, w2b);

    dim3 g3(HH / 4, GG, BB);                    // 14 x 16 x 4 = 896
    k3_involution<<<g3, 224>>>(x, out);
}

// round 9
// speedup vs baseline: 1.0491x; 1.0240x over previous
#include <cuda_runtime.h>
#include <cstdint>

#define BB 4
#define CC 256
#define HH 56
#define WW 56
#define CR 64          // C / 4
#define GG 16          // groups
#define GC 16
#define KK 7
#define K2T 49
#define M2 784         // GG * K2T
#define HW 3136        // HH * WW
#define PAD 3
#define N1 (BB * CR * HW)   // 802816

// Scratch (__device__ globals; no allocations allowed)
__device__ float g_p[2 * N1];               // K1 split-K partials
__device__ float g_w1[N1];                  // [B, Cr, HW]
__device__ float g_w2[BB * M2 * HW];        // [B, G*49, HW]

// ---------------------------------------------------------------------------
// K1a: partial conv1 over half the C range (split-K = 2). (round-8, unchanged)
// ---------------------------------------------------------------------------
__global__ __launch_bounds__(128) void k1a_partial(
        const float* __restrict__ x,
        const float* __restrict__ w1w) {
    __shared__ float As[64 * 68];    // [k][o]
    __shared__ float Bs[64 * 32];    // [k][px]

    const int tid = threadIdx.x;
    const int tx = tid & 7;
    const int ty = tid >> 3;
    const int px0 = blockIdx.x * 32;
    const int b = blockIdx.y;
    const int ks = blockIdx.z;

    float acc[4][4];
#pragma unroll
    for (int i = 0; i < 4; ++i)
#pragma unroll
        for (int u = 0; u < 4; ++u) acc[i][u] = 0.f;

    for (int kt = ks * 128; kt < ks * 128 + 128; kt += 64) {
        {
            int k = tid & 63;
            int oh = tid >> 6;
#pragma unroll
            for (int r = 0; r < 32; ++r) {
                int o = 2 * r + oh;
                As[k * 68 + o] = w1w[o * CC + kt + k];
            }
        }
        {
            int j = tid & 31;
            int kh = tid >> 5;
#pragma unroll
            for (int r = 0; r < 16; ++r) {
                int k = 4 * r + kh;
                Bs[k * 32 + j] = x[(size_t)(b * CC + kt + k) * HW + px0 + j];
            }
        }
        __syncthreads();

#pragma unroll 16
        for (int k = 0; k < 64; ++k) {
            float4 av = *(const float4*)&As[k * 68 + ty * 4];
            float4 bv = *(const float4*)&Bs[k * 32 + tx * 4];
            acc[0][0] = fmaf(av.x, bv.x, acc[0][0]);
            acc[0][1] = fmaf(av.x, bv.y, acc[0][1]);
            acc[0][2] = fmaf(av.x, bv.z, acc[0][2]);
            acc[0][3] = fmaf(av.x, bv.w, acc[0][3]);
            acc[1][0] = fmaf(av.y, bv.x, acc[1][0]);
            acc[1][1] = fmaf(av.y, bv.y, acc[1][1]);
            acc[1][2] = fmaf(av.y, bv.z, acc[1][2]);
            acc[1][3] = fmaf(av.y, bv.w, acc[1][3]);
            acc[2][0] = fmaf(av.z, bv.x, acc[2][0]);
            acc[2][1] = fmaf(av.z, bv.y, acc[2][1]);
            acc[2][2] = fmaf(av.z, bv.z, acc[2][2]);
            acc[2][3] = fmaf(av.z, bv.w, acc[2][3]);
            acc[3][0] = fmaf(av.w, bv.x, acc[3][0]);
            acc[3][1] = fmaf(av.w, bv.y, acc[3][1]);
            acc[3][2] = fmaf(av.w, bv.z, acc[3][2]);
            acc[3][3] = fmaf(av.w, bv.w, acc[3][3]);
        }
        __syncthreads();
    }

#pragma unroll
    for (int i = 0; i < 4; ++i) {
        int o = ty * 4 + i;
        float4 v = make_float4(acc[i][0], acc[i][1], acc[i][2], acc[i][3]);
        *(float4*)(g_p + (size_t)ks * N1 + (size_t)(b * CR + o) * HW
                   + px0 + tx * 4) = v;
    }
}

// ---------------------------------------------------------------------------
// K1b: sum partials + BN(eval) + ReLU. (round-8, unchanged)
// ---------------------------------------------------------------------------
__global__ __launch_bounds__(256) void k1b_bn_relu(
        const float* __restrict__ gamma,
        const float* __restrict__ beta,
        const float* __restrict__ mean,
        const float* __restrict__ var) {
    int i4 = blockIdx.x * blockDim.x + threadIdx.x;
    if (i4 >= N1 / 4) return;
    int idx = i4 * 4;
    int o = (idx / HW) % CR;

    float sc = gamma[o] * rsqrtf(var[o] + 1e-5f);
    float sh = beta[o] - mean[o] * sc;

    float4 p0 = *(const float4*)(g_p + idx);
    float4 p1 = *(const float4*)(g_p + N1 + idx);
    float4 v;
    v.x = fmaxf(fmaf(p0.x + p1.x, sc, sh), 0.f);
    v.y = fmaxf(fmaf(p0.y + p1.y, sc, sh), 0.f);
    v.z = fmaxf(fmaf(p0.z + p1.z, sc, sh), 0.f);
    v.w = fmaxf(fmaf(p0.w + p1.w, sc, sh), 0.f);
    *(float4*)(g_w1 + idx) = v;
}

// ---------------------------------------------------------------------------
// K2: w2 = conv2_1x1(w1) + bias. Tile 64o x 64px, 128 thr, 8x4. (round-8)
// ---------------------------------------------------------------------------
__global__ __launch_bounds__(128) void k2_conv2(
        const float* __restrict__ w2w,
        const float* __restrict__ w2b) {
    __shared__ float As[64 * 68];
    __shared__ float Bs[64 * 64];

    const int tid = threadIdx.x;
    const int tx = tid & 15;
    const int ty = tid >> 4;
    const int px0 = blockIdx.x * 64;
    const int o0 = blockIdx.y * 64;
    const int b = blockIdx.z;

    {
        int k = tid & 63;
        int oh = tid >> 6;
#pragma unroll
        for (int r = 0; r < 32; ++r) {
            int o = 2 * r + oh;
            As[k * 68 + o] = (o0 + o < M2) ? w2w[(o0 + o) * CR + k] : 0.f;
        }
    }
    {
        int j = tid & 63;
        int kh = tid >> 6;
#pragma unroll
        for (int r = 0; r < 32; ++r) {
            int k = 2 * r + kh;
            Bs[k * 64 + j] = g_w1[(size_t)(b * CR + k) * HW + px0 + j];
        }
    }
    __syncthreads();

    float acc[8][4];
#pragma unroll
    for (int i = 0; i < 8; ++i)
#pragma unroll
        for (int u = 0; u < 4; ++u) acc[i][u] = 0.f;

#pragma unroll 8
    for (int k = 0; k < 64; ++k) {
        float4 a0 = *(const float4*)&As[k * 68 + ty * 8];
        float4 a1 = *(const float4*)&As[k * 68 + ty * 8 + 4];
        float4 bv = *(const float4*)&Bs[k * 64 + tx * 4];
        float av[8] = {a0.x, a0.y, a0.z, a0.w, a1.x, a1.y, a1.z, a1.w};
#pragma unroll
        for (int i = 0; i < 8; ++i) {
            acc[i][0] = fmaf(av[i], bv.x, acc[i][0]);
            acc[i][1] = fmaf(av[i], bv.y, acc[i][1]);
            acc[i][2] = fmaf(av[i], bv.z, acc[i][2]);
            acc[i][3] = fmaf(av[i], bv.w, acc[i][3]);
        }
    }

#pragma unroll
    for (int i = 0; i < 8; ++i) {
        int o = o0 + ty * 8 + i;
        if (o >= M2) continue;
        float bias = w2b[o];
        float4 v;
        v.x = acc[i][0] + bias;
        v.y = acc[i][1] + bias;
        v.z = acc[i][2] + bias;
        v.w = acc[i][3] + bias;
        *(float4*)(g_w2 + (size_t)(b * M2 + o) * HW + px0 + tx * 4) = v;
    }
}

// ---------------------------------------------------------------------------
// K3: involution reduce. Block = (4-row band, group, batch); 224 threads.
// Thread = 4 px x 4 ch. NEW: register double-buffered weight prefetch —
// row ki+1's 7 LDG.128 issue before row ki's 112 FMAs, hiding L2 latency.
// ---------------------------------------------------------------------------
__global__ __launch_bounds__(224, 3) void k3_involution(
        const float* __restrict__ x,
        float* __restrict__ out) {
    __shared__ float xs[GC * 10 * 64];

    const int tid = threadIdx.x;
    const int h0 = blockIdx.x * 4;
    const int g = blockIdx.y;
    const int b = blockIdx.z;

    const float* xg = x + (size_t)(b * CC + g * GC) * HW;
    for (int i = tid; i < GC * 10 * 64; i += 224) {
        int ch = i / 640;
        int rem = i - ch * 640;
        int rr = rem >> 6;
        int c = rem & 63;
        int hh = h0 - 3 + rr;
        int ww = c - 3;
        float v = 0.f;
        if (hh >= 0 && hh < HH && ww >= 0 && ww < WW)
            v = xg[(size_t)ch * HW + hh * WW + ww];
        xs[i] = v;
    }
    __syncthreads();

    const int q = tid % 14;
    const int cg = (tid / 14) & 3;
    const int r = tid / 56;
    const int w0 = q * 4;
    const int h = h0 + r;

    const float* wg = g_w2 + ((size_t)(b * GG + g) * K2T) * HW + h * WW + w0;

    float acc[4][4];
#pragma unroll
    for (int c = 0; c < 4; ++c)
#pragma unroll
        for (int p = 0; p < 4; ++p) acc[c][p] = 0.f;

    // prime: taps of ki = 0
    float4 wcur[7], wnxt[7];
#pragma unroll
    for (int kj = 0; kj < KK; ++kj)
        wcur[kj] = *(const float4*)(wg + (size_t)kj * HW);

#pragma unroll
    for (int ki = 0; ki < KK; ++ki) {
        // prefetch next tap row before consuming the current one
        if (ki < KK - 1) {
#pragma unroll
            for (int kj = 0; kj < KK; ++kj)
                wnxt[kj] = *(const float4*)(wg + (size_t)((ki + 1) * KK + kj) * HW);
        }
#pragma unroll
        for (int c = 0; c < 4; ++c) {
            const float* xr = &xs[(cg * 4 + c) * 640 + (r + ki) * 64 + w0];
            float4 xa = *(const float4*)(xr);
            float4 xb = *(const float4*)(xr + 4);
            float4 xc = *(const float4*)(xr + 8);
            float xw[12] = {xa.x, xa.y, xa.z, xa.w,
                            xb.x, xb.y, xb.z, xb.w,
                            xc.x, xc.y, xc.z, xc.w};
#pragma unroll
            for (int kj = 0; kj < KK; ++kj) {
                acc[c][0] = fmaf(wcur[kj].x, xw[kj + 0], acc[c][0]);
                acc[c][1] = fmaf(wcur[kj].y, xw[kj + 1], acc[c][1]);
                acc[c][2] = fmaf(wcur[kj].z, xw[kj + 2], acc[c][2]);
                acc[c][3] = fmaf(wcur[kj].w, xw[kj + 3], acc[c][3]);
            }
        }
#pragma unroll
        for (int kj = 0; kj < KK; ++kj)
            wcur[kj] = wnxt[kj];
    }

#pragma unroll
    for (int c = 0; c < 4; ++c) {
        float4 v = make_float4(acc[c][0], acc[c][1], acc[c][2], acc[c][3]);
        *(float4*)(out + (size_t)(b * CC + g * GC + cg * 4 + c) * HW
                   + h * WW + w0) = v;
    }
}

// ---------------------------------------------------------------------------
extern "C" void kernel_launch(void* const* d_in, const int* in_sizes, int n_in,
                              void* d_out, int out_size) {
    const float* x     = (const float*)d_in[0];
    const float* w1w   = (const float*)d_in[1];
    const float* gamma = (const float*)d_in[2];
    const float* beta  = (const float*)d_in[3];
    const float* mean  = (const float*)d_in[4];
    const float* var   = (const float*)d_in[5];
    const float* w2w   = (const float*)d_in[6];
    const float* w2b   = (const float*)d_in[7];
    float* out = (float*)d_out;

    dim3 g1(HW / 32, BB, 2);                    // 98 x 4 x 2 = 784
    k1a_partial<<<g1, 128>>>(x, w1w);

    k1b_bn_relu<<<(N1 / 4 + 255) / 256, 256>>>(gamma, beta, mean, var);

    dim3 g2(HW / 64, (M2 + 63) / 64, BB);       // 49 x 13 x 4 = 2548
    k2_conv2<<<g2, 128>>>(w2w, w2b);

    dim3 g3(HH / 4, GG, BB);                    // 14 x 16 x 4 = 896
    k3_involution<<<g3, 224>>>(x, out);
}